// round 1
// baseline (speedup 1.0000x reference)
#include <cuda_runtime.h>
#include <math.h>

#define B 16
#define L 128
#define H 1024
#define V 50257
#define T (L-1)

// ---- scratch (no allocations allowed) ----
__device__ float g_x0[B * H];
__device__ float g_h0[B * H];
__device__ float g_gi[B * 3 * H];
__device__ float g_gh[B * 3 * H];
__device__ float g_h1[B * H];
__device__ float g_logits[(size_t)B * V];
__device__ float g_m[B];
__device__ float g_l[B];

// ---------------------------------------------------------------------------
// K1: x0 = relu(emb[input[:,0]]);  h0[b,h] = sum_l hidden[b,l,h]*bw[l] + bb
// one thread per (b,h); coalesced over h.
// ---------------------------------------------------------------------------
__global__ void k1_embed_bridge(const int* __restrict__ input,
                                const float* __restrict__ hidden,
                                const float* __restrict__ emb,
                                const float* __restrict__ bridge_w,
                                const float* __restrict__ bridge_b) {
    __shared__ float bw[L];
    int tid = threadIdx.x;
    if (tid < L) bw[tid] = bridge_w[tid];
    __syncthreads();

    int i = blockIdx.x * blockDim.x + tid;   // 0 .. B*H-1
    int b = i >> 10;
    int h = i & (H - 1);

    int tok = input[b * L];                  // input[:,0]
    g_x0[i] = fmaxf(emb[(size_t)tok * H + h], 0.0f);

    const float* hp = hidden + (size_t)b * L * H + h;
    float a0 = 0.f, a1 = 0.f, a2 = 0.f, a3 = 0.f;
    #pragma unroll
    for (int l = 0; l < L; l += 4) {
        a0 += hp[(l + 0) * H] * bw[l + 0];
        a1 += hp[(l + 1) * H] * bw[l + 1];
        a2 += hp[(l + 2) * H] * bw[l + 2];
        a3 += hp[(l + 3) * H] * bw[l + 3];
    }
    g_h0[i] = (a0 + a1) + (a2 + a3) + bridge_b[0];
}

// ---------------------------------------------------------------------------
// K2: gi = x0 @ w_ih^T + b_ih ; gh = h0 @ w_hh^T + b_hh   (both [B, 3H])
// warp computes 2 output rows (j) for all 16 batches; w read exactly once,
// x0/h0 (128 KB) served from L1 across the block's warps.
// grid = 3072 rows / (8 warps * 2 rows) = 192 blocks, 256 thr.
// ---------------------------------------------------------------------------
__global__ void k2_gates_mm(const float* __restrict__ w_ih,
                            const float* __restrict__ w_hh,
                            const float* __restrict__ b_ih,
                            const float* __restrict__ b_hh) {
    int warp = threadIdx.x >> 5;
    int lane = threadIdx.x & 31;
    int j0 = (blockIdx.x * 8 + warp) * 2;      // rows j0, j0+1

    float ai0[B], ai1[B], ah0[B], ah1[B];
    #pragma unroll
    for (int b = 0; b < B; b++) { ai0[b] = ai1[b] = ah0[b] = ah1[b] = 0.f; }

    for (int i = 0; i < 8; i++) {
        int k = i * 128 + lane * 4;
        float4 wi0 = *(const float4*)(w_ih + (size_t)(j0 + 0) * H + k);
        float4 wi1 = *(const float4*)(w_ih + (size_t)(j0 + 1) * H + k);
        float4 wh0 = *(const float4*)(w_hh + (size_t)(j0 + 0) * H + k);
        float4 wh1 = *(const float4*)(w_hh + (size_t)(j0 + 1) * H + k);
        #pragma unroll
        for (int b = 0; b < B; b++) {
            float4 x = *(const float4*)(g_x0 + b * H + k);
            float4 h = *(const float4*)(g_h0 + b * H + k);
            ai0[b] += wi0.x * x.x + wi0.y * x.y + wi0.z * x.z + wi0.w * x.w;
            ai1[b] += wi1.x * x.x + wi1.y * x.y + wi1.z * x.z + wi1.w * x.w;
            ah0[b] += wh0.x * h.x + wh0.y * h.y + wh0.z * h.z + wh0.w * h.w;
            ah1[b] += wh1.x * h.x + wh1.y * h.y + wh1.z * h.z + wh1.w * h.w;
        }
    }

    #pragma unroll
    for (int b = 0; b < B; b++) {
        #pragma unroll
        for (int o = 16; o; o >>= 1) {
            ai0[b] += __shfl_xor_sync(0xffffffffu, ai0[b], o);
            ai1[b] += __shfl_xor_sync(0xffffffffu, ai1[b], o);
            ah0[b] += __shfl_xor_sync(0xffffffffu, ah0[b], o);
            ah1[b] += __shfl_xor_sync(0xffffffffu, ah1[b], o);
        }
    }

    if (lane == 0) {
        float bi0 = b_ih[j0], bi1 = b_ih[j0 + 1];
        float bh0 = b_hh[j0], bh1 = b_hh[j0 + 1];
        #pragma unroll
        for (int b = 0; b < B; b++) {
            g_gi[b * 3 * H + j0]     = ai0[b] + bi0;
            g_gi[b * 3 * H + j0 + 1] = ai1[b] + bi1;
            g_gh[b * 3 * H + j0]     = ah0[b] + bh0;
            g_gh[b * 3 * H + j0 + 1] = ah1[b] + bh1;
        }
    }
}

// ---------------------------------------------------------------------------
// K3: GRU cell gate math -> h1 [B,H]
// ---------------------------------------------------------------------------
__global__ void k3_gru() {
    int i = blockIdx.x * blockDim.x + threadIdx.x;  // 0..B*H-1
    int b = i >> 10;
    int h = i & (H - 1);
    int base = b * 3 * H + h;
    float ir = g_gi[base], iz = g_gi[base + H], in_ = g_gi[base + 2 * H];
    float hr = g_gh[base], hz = g_gh[base + H], hn  = g_gh[base + 2 * H];
    float r = 1.f / (1.f + expf(-(ir + hr)));
    float z = 1.f / (1.f + expf(-(iz + hz)));
    float n = tanhf(in_ + r * hn);
    g_h1[i] = (1.f - z) * n + z * g_h0[i];
}

// ---------------------------------------------------------------------------
// K4: logits[b,v] = h1[b,:] . proj_w[v,:] + proj_b[v]
// h1 in smem (64 KB); warp per vocab row; proj_w streamed with __ldcs.
// ---------------------------------------------------------------------------
__global__ void k4_proj(const float* __restrict__ proj_w,
                        const float* __restrict__ proj_b) {
    extern __shared__ float hs[];                 // B*H floats
    for (int i = threadIdx.x; i < B * H; i += blockDim.x) hs[i] = g_h1[i];
    __syncthreads();

    int warp = threadIdx.x >> 5;
    int lane = threadIdx.x & 31;

    for (int v = blockIdx.x * 8 + warp; v < V; v += gridDim.x * 8) {
        float acc[B];
        #pragma unroll
        for (int b = 0; b < B; b++) acc[b] = 0.f;

        const float4* pw = (const float4*)(proj_w + (size_t)v * H);
        #pragma unroll
        for (int i = 0; i < 8; i++) {
            float4 p = __ldcs(pw + i * 32 + lane);
            #pragma unroll
            for (int b = 0; b < B; b++) {
                float4 x = *(const float4*)(hs + b * H + i * 128 + lane * 4);
                acc[b] += p.x * x.x + p.y * x.y + p.z * x.z + p.w * x.w;
            }
        }
        #pragma unroll
        for (int b = 0; b < B; b++) {
            #pragma unroll
            for (int o = 16; o; o >>= 1)
                acc[b] += __shfl_xor_sync(0xffffffffu, acc[b], o);
        }
        if (lane == 0) {
            float pb = proj_b[v];
            #pragma unroll
            for (int b = 0; b < B; b++)
                g_logits[(size_t)b * V + v] = acc[b] + pb;
        }
    }
}

// ---------------------------------------------------------------------------
// K5: per-batch max and log-sum-exp over V (logits are hot in L2)
// ---------------------------------------------------------------------------
__global__ void k5_lse() {
    int b = blockIdx.x;
    __shared__ float red[256];
    const float* lg = g_logits + (size_t)b * V;

    float m = -1e30f;
    for (int v = threadIdx.x; v < V; v += 256) m = fmaxf(m, lg[v]);
    red[threadIdx.x] = m;
    __syncthreads();
    for (int s = 128; s; s >>= 1) {
        if (threadIdx.x < s) red[threadIdx.x] = fmaxf(red[threadIdx.x], red[threadIdx.x + s]);
        __syncthreads();
    }
    m = red[0];
    __syncthreads();

    float sum = 0.f;
    for (int v = threadIdx.x; v < V; v += 256) sum += expf(lg[v] - m);
    red[threadIdx.x] = sum;
    __syncthreads();
    for (int s = 128; s; s >>= 1) {
        if (threadIdx.x < s) red[threadIdx.x] += red[threadIdx.x + s];
        __syncthreads();
    }
    if (threadIdx.x == 0) { g_m[b] = m; g_l[b] = logf(red[0]); }
}

// ---------------------------------------------------------------------------
// K6: out[b,t,v] = logits[b,v] - m[b] - lse[b]  broadcast over t (127)
// one thread per (b,v), 127 coalesced stores.
// ---------------------------------------------------------------------------
__global__ void k6_out(float* __restrict__ out) {
    int v = blockIdx.x * blockDim.x + threadIdx.x;
    int b = blockIdx.y;
    if (v >= V) return;
    float val = g_logits[(size_t)b * V + v] - g_m[b] - g_l[b];
    float* o = out + (size_t)b * T * V + v;
    #pragma unroll 8
    for (int t = 0; t < T; t++) o[(size_t)t * V] = val;
}

// ---------------------------------------------------------------------------
extern "C" void kernel_launch(void* const* d_in, const int* in_sizes, int n_in,
                              void* d_out, int out_size) {
    const int*   input    = (const int*)d_in[0];
    const float* hidden   = (const float*)d_in[1];
    const float* emb      = (const float*)d_in[2];
    const float* bridge_w = (const float*)d_in[3];
    const float* bridge_b = (const float*)d_in[4];
    const float* w_ih     = (const float*)d_in[5];
    const float* w_hh     = (const float*)d_in[6];
    const float* b_ih     = (const float*)d_in[7];
    const float* b_hh     = (const float*)d_in[8];
    const float* proj_w   = (const float*)d_in[9];
    const float* proj_b   = (const float*)d_in[10];
    float* out = (float*)d_out;

    cudaFuncSetAttribute(k4_proj, cudaFuncAttributeMaxDynamicSharedMemorySize,
                         B * H * (int)sizeof(float));

    k1_embed_bridge<<<(B * H) / 256, 256>>>(input, hidden, emb, bridge_w, bridge_b);
    k2_gates_mm<<<192, 256>>>(w_ih, w_hh, b_ih, b_hh);
    k3_gru<<<(B * H) / 256, 256>>>();
    k4_proj<<<592, 256, B * H * sizeof(float)>>>(proj_w, proj_b);
    k5_lse<<<B, 256>>>();
    dim3 g6((V + 255) / 256, B);
    k6_out<<<g6, 256>>>(out);
}

// round 2
// speedup vs baseline: 1.2109x; 1.2109x over previous
#include <cuda_runtime.h>
#include <math.h>

#define B 16
#define L 128
#define H 1024
#define V 50257
#define T (L-1)

// ---- scratch (no allocations allowed) ----
__device__ float g_x0[B * H];
__device__ float g_h0[B * H];
__device__ float g_h0p[4][B * H];
__device__ float g_gi[B * 3 * H];
__device__ float g_gh[B * 3 * H];
__device__ float g_h1[B * H];
__device__ float g_logits[(size_t)B * V];
__device__ float g_m[B];
__device__ float g_l[B];

// ---------------------------------------------------------------------------
// K1a: partial bridge reduction. grid = (64, 4); chunk c covers l in [32c,32c+32)
// h0p[c][b,h] = sum_l hidden[b,l,h]*bw[l]
// ---------------------------------------------------------------------------
__global__ void k1a_bridge_part(const float* __restrict__ hidden,
                                const float* __restrict__ bridge_w) {
    __shared__ float bw[32];
    int c = blockIdx.y;
    if (threadIdx.x < 32) bw[threadIdx.x] = bridge_w[c * 32 + threadIdx.x];
    __syncthreads();

    int i = blockIdx.x * 256 + threadIdx.x;   // 0 .. B*H-1
    int b = i >> 10;
    int h = i & (H - 1);
    const float* hp = hidden + (size_t)b * L * H + (size_t)(c * 32) * H + h;
    float a0 = 0.f, a1 = 0.f, a2 = 0.f, a3 = 0.f;
    #pragma unroll
    for (int l = 0; l < 32; l += 4) {
        a0 += hp[(l + 0) * H] * bw[l + 0];
        a1 += hp[(l + 1) * H] * bw[l + 1];
        a2 += hp[(l + 2) * H] * bw[l + 2];
        a3 += hp[(l + 3) * H] * bw[l + 3];
    }
    g_h0p[c][i] = (a0 + a1) + (a2 + a3);
}

// ---------------------------------------------------------------------------
// K1b: combine partials + bias; also x0 = relu(emb[input[:,0]])
// ---------------------------------------------------------------------------
__global__ void k1b_combine(const int* __restrict__ input,
                            const float* __restrict__ emb,
                            const float* __restrict__ bridge_b) {
    int i = blockIdx.x * 256 + threadIdx.x;
    int b = i >> 10;
    int h = i & (H - 1);
    int tok = input[b * L];
    g_x0[i] = fmaxf(emb[(size_t)tok * H + h], 0.0f);
    g_h0[i] = (g_h0p[0][i] + g_h0p[1][i]) + (g_h0p[2][i] + g_h0p[3][i]) + bridge_b[0];
}

// ---------------------------------------------------------------------------
// K2: gi = x0 @ w_ih^T + b_ih ; gh = h0 @ w_hh^T + b_hh   (both [B, 3H])
// warp computes 2 output rows for all 16 batches.
// ---------------------------------------------------------------------------
__global__ void k2_gates_mm(const float* __restrict__ w_ih,
                            const float* __restrict__ w_hh,
                            const float* __restrict__ b_ih,
                            const float* __restrict__ b_hh) {
    int warp = threadIdx.x >> 5;
    int lane = threadIdx.x & 31;
    int j0 = (blockIdx.x * 8 + warp) * 2;

    float ai0[B], ai1[B], ah0[B], ah1[B];
    #pragma unroll
    for (int b = 0; b < B; b++) { ai0[b] = ai1[b] = ah0[b] = ah1[b] = 0.f; }

    for (int i = 0; i < 8; i++) {
        int k = i * 128 + lane * 4;
        float4 wi0 = *(const float4*)(w_ih + (size_t)(j0 + 0) * H + k);
        float4 wi1 = *(const float4*)(w_ih + (size_t)(j0 + 1) * H + k);
        float4 wh0 = *(const float4*)(w_hh + (size_t)(j0 + 0) * H + k);
        float4 wh1 = *(const float4*)(w_hh + (size_t)(j0 + 1) * H + k);
        #pragma unroll
        for (int b = 0; b < B; b++) {
            float4 x = *(const float4*)(g_x0 + b * H + k);
            float4 h = *(const float4*)(g_h0 + b * H + k);
            ai0[b] += wi0.x * x.x + wi0.y * x.y + wi0.z * x.z + wi0.w * x.w;
            ai1[b] += wi1.x * x.x + wi1.y * x.y + wi1.z * x.z + wi1.w * x.w;
            ah0[b] += wh0.x * h.x + wh0.y * h.y + wh0.z * h.z + wh0.w * h.w;
            ah1[b] += wh1.x * h.x + wh1.y * h.y + wh1.z * h.z + wh1.w * h.w;
        }
    }

    #pragma unroll
    for (int b = 0; b < B; b++) {
        #pragma unroll
        for (int o = 16; o; o >>= 1) {
            ai0[b] += __shfl_xor_sync(0xffffffffu, ai0[b], o);
            ai1[b] += __shfl_xor_sync(0xffffffffu, ai1[b], o);
            ah0[b] += __shfl_xor_sync(0xffffffffu, ah0[b], o);
            ah1[b] += __shfl_xor_sync(0xffffffffu, ah1[b], o);
        }
    }

    if (lane == 0) {
        float bi0 = b_ih[j0], bi1 = b_ih[j0 + 1];
        float bh0 = b_hh[j0], bh1 = b_hh[j0 + 1];
        #pragma unroll
        for (int b = 0; b < B; b++) {
            g_gi[b * 3 * H + j0]     = ai0[b] + bi0;
            g_gi[b * 3 * H + j0 + 1] = ai1[b] + bi1;
            g_gh[b * 3 * H + j0]     = ah0[b] + bh0;
            g_gh[b * 3 * H + j0 + 1] = ah1[b] + bh1;
        }
    }
}

// ---------------------------------------------------------------------------
// K3: GRU cell gate math -> h1 [B,H]
// ---------------------------------------------------------------------------
__global__ void k3_gru() {
    int i = blockIdx.x * blockDim.x + threadIdx.x;
    int b = i >> 10;
    int h = i & (H - 1);
    int base = b * 3 * H + h;
    float ir = g_gi[base], iz = g_gi[base + H], in_ = g_gi[base + 2 * H];
    float hr = g_gh[base], hz = g_gh[base + H], hn  = g_gh[base + 2 * H];
    float r = 1.f / (1.f + expf(-(ir + hr)));
    float z = 1.f / (1.f + expf(-(iz + hz)));
    float n = tanhf(in_ + r * hn);
    g_h1[i] = (1.f - z) * n + z * g_h0[i];
}

// ---------------------------------------------------------------------------
// K4: logits[b,v] = h1[b,:] . proj_w[v,:] + proj_b[v]
// 4 vocab rows per warp: each smem float4 of h1 feeds 4 rows -> 4x less
// crossbar traffic than 1 row/warp. proj_w streamed with __ldcs.
// ---------------------------------------------------------------------------
__global__ __launch_bounds__(256, 2)
void k4_proj(const float* __restrict__ proj_w,
             const float* __restrict__ proj_b) {
    extern __shared__ float hs[];                 // B*H floats = 64KB
    for (int i = threadIdx.x; i < B * H; i += 256) hs[i] = g_h1[i];
    __syncthreads();

    int warp = threadIdx.x >> 5;
    int lane = threadIdx.x & 31;
    int v0 = (blockIdx.x * 8 + warp) * 4;
    if (v0 >= V) return;

    int r1 = min(v0 + 1, V - 1);
    int r2 = min(v0 + 2, V - 1);
    int r3 = min(v0 + 3, V - 1);
    const float4* w0 = (const float4*)(proj_w + (size_t)v0 * H);
    const float4* w1 = (const float4*)(proj_w + (size_t)r1 * H);
    const float4* w2 = (const float4*)(proj_w + (size_t)r2 * H);
    const float4* w3 = (const float4*)(proj_w + (size_t)r3 * H);

    float a0[B], a1[B], a2[B], a3[B];
    #pragma unroll
    for (int b = 0; b < B; b++) { a0[b] = a1[b] = a2[b] = a3[b] = 0.f; }

    #pragma unroll
    for (int i = 0; i < 8; i++) {
        int kq = i * 32 + lane;                    // float4 index into row
        float4 p0 = __ldcs(w0 + kq);
        float4 p1 = __ldcs(w1 + kq);
        float4 p2 = __ldcs(w2 + kq);
        float4 p3 = __ldcs(w3 + kq);
        #pragma unroll
        for (int b = 0; b < B; b++) {
            float4 x = ((const float4*)(hs + b * H))[kq];
            a0[b] += p0.x * x.x + p0.y * x.y + p0.z * x.z + p0.w * x.w;
            a1[b] += p1.x * x.x + p1.y * x.y + p1.z * x.z + p1.w * x.w;
            a2[b] += p2.x * x.x + p2.y * x.y + p2.z * x.z + p2.w * x.w;
            a3[b] += p3.x * x.x + p3.y * x.y + p3.z * x.z + p3.w * x.w;
        }
    }

    #pragma unroll
    for (int b = 0; b < B; b++) {
        #pragma unroll
        for (int o = 16; o; o >>= 1) {
            a0[b] += __shfl_xor_sync(0xffffffffu, a0[b], o);
            a1[b] += __shfl_xor_sync(0xffffffffu, a1[b], o);
            a2[b] += __shfl_xor_sync(0xffffffffu, a2[b], o);
            a3[b] += __shfl_xor_sync(0xffffffffu, a3[b], o);
        }
    }

    if (lane == 0) {
        float pb0 = proj_b[v0];
        float pb1 = proj_b[r1];
        float pb2 = proj_b[r2];
        float pb3 = proj_b[r3];
        #pragma unroll
        for (int b = 0; b < B; b++) {
            float* lg = g_logits + (size_t)b * V;
            lg[v0] = a0[b] + pb0;
            if (v0 + 1 < V) lg[v0 + 1] = a1[b] + pb1;
            if (v0 + 2 < V) lg[v0 + 2] = a2[b] + pb2;
            if (v0 + 3 < V) lg[v0 + 3] = a3[b] + pb3;
        }
    }
}

// ---------------------------------------------------------------------------
// K5: per-batch max and log-sum-exp over V (logits hot in L2)
// ---------------------------------------------------------------------------
__global__ void k5_lse() {
    int b = blockIdx.x;
    __shared__ float red[256];
    const float* lg = g_logits + (size_t)b * V;

    float m = -1e30f;
    for (int v = threadIdx.x; v < V; v += 256) m = fmaxf(m, lg[v]);
    red[threadIdx.x] = m;
    __syncthreads();
    for (int s = 128; s; s >>= 1) {
        if (threadIdx.x < s) red[threadIdx.x] = fmaxf(red[threadIdx.x], red[threadIdx.x + s]);
        __syncthreads();
    }
    m = red[0];
    __syncthreads();

    float sum = 0.f;
    for (int v = threadIdx.x; v < V; v += 256) sum += expf(lg[v] - m);
    red[threadIdx.x] = sum;
    __syncthreads();
    for (int s = 128; s; s >>= 1) {
        if (threadIdx.x < s) red[threadIdx.x] += red[threadIdx.x + s];
        __syncthreads();
    }
    if (threadIdx.x == 0) { g_m[b] = m; g_l[b] = logf(red[0]); }
}

// ---------------------------------------------------------------------------
// K6: out[b,t,v] = logits[b,v] - m[b] - lse[b]  broadcast over t (127)
// one thread per (b,v); 127 coalesced strided stores (DRAM-store-bound).
// ---------------------------------------------------------------------------
__global__ void k6_out(float* __restrict__ out) {
    int v = blockIdx.x * blockDim.x + threadIdx.x;
    int b = blockIdx.y;
    if (v >= V) return;
    float val = g_logits[(size_t)b * V + v] - g_m[b] - g_l[b];
    float* o = out + (size_t)b * T * V + v;
    #pragma unroll 8
    for (int t = 0; t < T; t++) o[(size_t)t * V] = val;
}

// ---------------------------------------------------------------------------
extern "C" void kernel_launch(void* const* d_in, const int* in_sizes, int n_in,
                              void* d_out, int out_size) {
    const int*   input    = (const int*)d_in[0];
    const float* hidden   = (const float*)d_in[1];
    const float* emb      = (const float*)d_in[2];
    const float* bridge_w = (const float*)d_in[3];
    const float* bridge_b = (const float*)d_in[4];
    const float* w_ih     = (const float*)d_in[5];
    const float* w_hh     = (const float*)d_in[6];
    const float* b_ih     = (const float*)d_in[7];
    const float* b_hh     = (const float*)d_in[8];
    const float* proj_w   = (const float*)d_in[9];
    const float* proj_b   = (const float*)d_in[10];
    float* out = (float*)d_out;

    cudaFuncSetAttribute(k4_proj, cudaFuncAttributeMaxDynamicSharedMemorySize,
                         B * H * (int)sizeof(float));

    dim3 g1(64, 4);
    k1a_bridge_part<<<g1, 256>>>(hidden, bridge_w);
    k1b_combine<<<64, 256>>>(input, emb, bridge_b);
    k2_gates_mm<<<192, 256>>>(w_ih, w_hh, b_ih, b_hh);
    k3_gru<<<(B * H) / 256, 256>>>();
    int blocks4 = (V + 31) / 32;   // 8 warps x 4 rows per block
    k4_proj<<<blocks4, 256, B * H * sizeof(float)>>>(proj_w, proj_b);
    k5_lse<<<B, 256>>>();
    dim3 g6((V + 255) / 256, B);
    k6_out<<<g6, 256>>>(out);
}